// round 1
// baseline (speedup 1.0000x reference)
#include <cuda_runtime.h>
#include <math.h>

// Problem constants
#define BATCH 4
#define CCH   512
#define NSP   4096      // 64*64
#define GROUPS 32
#define GSIZE  65536    // (CCH/GROUPS)*NSP = 16*4096

static const long CN = (long)CCH * NSP;   // 2,097,152 per-batch [C,N] stride
static const long NN = (long)NSP * NSP;   // 16,777,216 per-batch [N,N] stride

// Scratch (device globals — allocation-free per harness rules)
__device__ float g_h[BATCH * CCH * NSP];   // groupnorm output
__device__ float g_q[BATCH * CCH * NSP];
__device__ float g_k[BATCH * CCH * NSP];
__device__ float g_v[BATCH * CCH * NSP];
__device__ float g_o[BATCH * CCH * NSP];   // attention output (pre-proj)
__device__ float g_s[BATCH * (long)NSP * NSP]; // scores / attn (268 MB)

// ---------------------------------------------------------------------------
// GroupNorm: one block per (b, group). Group data is a contiguous 65536-float
// chunk (channels within a group are adjacent, each channel is 4096 floats).
// ---------------------------------------------------------------------------
__global__ void gn_kernel(const float* __restrict__ x,
                          const float* __restrict__ gamma,
                          const float* __restrict__ beta,
                          float* __restrict__ out)
{
    const int bg  = blockIdx.x;               // b*32 + g
    const long base = (long)bg * GSIZE;
    const int tid = threadIdx.x;              // 256 threads

    float s = 0.f, ss = 0.f;
    for (int i = tid * 4; i < GSIZE; i += 256 * 4) {
        float4 v = *(const float4*)(x + base + i);
        s  += v.x + v.y + v.z + v.w;
        ss += v.x*v.x + v.y*v.y + v.z*v.z + v.w*v.w;
    }
    __shared__ float rs[256], rq[256];
    rs[tid] = s; rq[tid] = ss;
    __syncthreads();
    for (int o = 128; o > 0; o >>= 1) {
        if (tid < o) { rs[tid] += rs[tid + o]; rq[tid] += rq[tid + o]; }
        __syncthreads();
    }
    __shared__ float smu, srstd;
    if (tid == 0) {
        float mu  = rs[0] * (1.f / GSIZE);
        float var = rq[0] * (1.f / GSIZE) - mu * mu;
        smu = mu;
        srstd = rsqrtf(var + 1e-6f);
    }
    __syncthreads();
    const float mu = smu, rstd = srstd;
    const int cbase = (bg & (GROUPS - 1)) * (CCH / GROUPS);

    for (int i = tid * 4; i < GSIZE; i += 256 * 4) {
        float4 v = *(const float4*)(x + base + i);
        int c = cbase + (i >> 12);           // i / 4096 (constant across float4)
        float ga = gamma[c] * rstd;
        float be = beta[c] - mu * ga;
        v.x = v.x * ga + be;
        v.y = v.y * ga + be;
        v.z = v.z * ga + be;
        v.w = v.w * ga + be;
        *(float4*)(out + base + i) = v;
    }
}

// ---------------------------------------------------------------------------
// SGEMM: C[m,n] = alpha * sum_k A(m,k)*B(k,n) + bias[m] + residual[m,n]
//   TA: A(m,k) = A[k*lda + m]   else A[m*lda + k]
//   TB: B(k,n) = B[n*ldb + k]   else B[k*ldb + n]
// Block tile 128x128, K-tile 8, 256 threads, 8x8 micro-tile split 64 apart
// (conflict-free LDS.128 on both operands). All dims are multiples of tiles.
// ---------------------------------------------------------------------------
template<bool TA, bool TB>
__global__ void __launch_bounds__(256)
sgemm(const float* __restrict__ A, const float* __restrict__ B,
      float* __restrict__ C,
      int M, int N, int K, int lda, int ldb, int ldc,
      long strideA, long strideB, long strideC, long strideR,
      float alpha, const float* __restrict__ bias,
      const float* __restrict__ residual)
{
    __shared__ float As[8][128];
    __shared__ float Bs[8][128];

    const int bz = blockIdx.z;
    A += bz * strideA;
    B += bz * strideB;
    C += bz * strideC;
    const float* R = residual ? (residual + bz * strideR) : nullptr;

    const int m0 = blockIdx.y * 128;
    const int n0 = blockIdx.x * 128;
    const int t  = threadIdx.x;
    const int tx = t & 15;
    const int ty = t >> 4;

    float acc[8][8];
#pragma unroll
    for (int i = 0; i < 8; i++)
#pragma unroll
        for (int j = 0; j < 8; j++) acc[i][j] = 0.f;

    const int nk = K >> 3;
    for (int kt = 0; kt < nk; kt++) {
        const int k0 = kt << 3;
        // ---- load A tile into As[k][m]
        if (TA) {
            int k  = t >> 5;
            int mm = (t & 31) << 2;
            float4 v = *(const float4*)(A + (long)(k0 + k) * lda + m0 + mm);
            *(float4*)&As[k][mm] = v;
        } else {
            int m  = t >> 1;
            int kk = (t & 1) << 2;
            float4 v = *(const float4*)(A + (long)(m0 + m) * lda + k0 + kk);
            As[kk + 0][m] = v.x;
            As[kk + 1][m] = v.y;
            As[kk + 2][m] = v.z;
            As[kk + 3][m] = v.w;
        }
        // ---- load B tile into Bs[k][n]
        if (TB) {
            int n  = t >> 1;
            int kk = (t & 1) << 2;
            float4 v = *(const float4*)(B + (long)(n0 + n) * ldb + k0 + kk);
            Bs[kk + 0][n] = v.x;
            Bs[kk + 1][n] = v.y;
            Bs[kk + 2][n] = v.z;
            Bs[kk + 3][n] = v.w;
        } else {
            int k  = t >> 5;
            int nn = (t & 31) << 2;
            float4 v = *(const float4*)(B + (long)(k0 + k) * ldb + n0 + nn);
            *(float4*)&Bs[k][nn] = v;
        }
        __syncthreads();

#pragma unroll
        for (int kk = 0; kk < 8; kk++) {
            float a[8], b[8];
            *(float4*)&a[0] = *(const float4*)&As[kk][ty * 4];
            *(float4*)&a[4] = *(const float4*)&As[kk][64 + ty * 4];
            *(float4*)&b[0] = *(const float4*)&Bs[kk][tx * 4];
            *(float4*)&b[4] = *(const float4*)&Bs[kk][64 + tx * 4];
#pragma unroll
            for (int i = 0; i < 8; i++)
#pragma unroll
                for (int j = 0; j < 8; j++)
                    acc[i][j] += a[i] * b[j];
        }
        __syncthreads();
    }

    // ---- epilogue
#pragma unroll
    for (int i = 0; i < 8; i++) {
        int m = m0 + ((i < 4) ? (ty * 4 + i) : (64 + ty * 4 + (i - 4)));
        float bv = bias ? bias[m] : 0.f;
#pragma unroll
        for (int jj = 0; jj < 2; jj++) {
            int n = n0 + jj * 64 + tx * 4;
            float4 o;
            o.x = acc[i][jj * 4 + 0] * alpha + bv;
            o.y = acc[i][jj * 4 + 1] * alpha + bv;
            o.z = acc[i][jj * 4 + 2] * alpha + bv;
            o.w = acc[i][jj * 4 + 3] * alpha + bv;
            if (R) {
                float4 r = *(const float4*)(R + (long)m * ldc + n);
                o.x += r.x; o.y += r.y; o.z += r.z; o.w += r.w;
            }
            *(float4*)(C + (long)m * ldc + n) = o;
        }
    }
}

// ---------------------------------------------------------------------------
// Row softmax over 4096 columns. One block per row, row staged in smem.
// ---------------------------------------------------------------------------
__global__ void softmax_kernel(float* __restrict__ s)
{
    const long row = blockIdx.x;
    float* p = s + row * (long)NSP;
    const int tid = threadIdx.x;      // 256

    __shared__ float buf[NSP];
    __shared__ float red[256];

    float m = -1e30f;
    for (int i = tid * 4; i < NSP; i += 1024) {
        float4 v = *(const float4*)(p + i);
        *(float4*)(buf + i) = v;
        m = fmaxf(m, fmaxf(fmaxf(v.x, v.y), fmaxf(v.z, v.w)));
    }
    red[tid] = m;
    __syncthreads();
    for (int o = 128; o > 0; o >>= 1) {
        if (tid < o) red[tid] = fmaxf(red[tid], red[tid + o]);
        __syncthreads();
    }
    m = red[0];
    __syncthreads();

    float sum = 0.f;
    for (int i = tid * 4; i < NSP; i += 1024) {
        float4 v = *(const float4*)(buf + i);
        v.x = __expf(v.x - m);
        v.y = __expf(v.y - m);
        v.z = __expf(v.z - m);
        v.w = __expf(v.w - m);
        *(float4*)(buf + i) = v;
        sum += v.x + v.y + v.z + v.w;
    }
    red[tid] = sum;
    __syncthreads();
    for (int o = 128; o > 0; o >>= 1) {
        if (tid < o) red[tid] += red[tid + o];
        __syncthreads();
    }
    const float inv = 1.f / red[0];

    for (int i = tid * 4; i < NSP; i += 1024) {
        float4 v = *(const float4*)(buf + i);
        v.x *= inv; v.y *= inv; v.z *= inv; v.w *= inv;
        *(float4*)(p + i) = v;
    }
}

// ---------------------------------------------------------------------------
extern "C" void kernel_launch(void* const* d_in, const int* in_sizes, int n_in,
                              void* d_out, int out_size)
{
    const float* x     = (const float*)d_in[0];
    const float* gamma = (const float*)d_in[1];
    const float* beta  = (const float*)d_in[2];
    const float* wq    = (const float*)d_in[3];
    const float* bq    = (const float*)d_in[4];
    const float* wk    = (const float*)d_in[5];
    const float* bk    = (const float*)d_in[6];
    const float* wv    = (const float*)d_in[7];
    const float* bv    = (const float*)d_in[8];
    const float* wp    = (const float*)d_in[9];
    const float* bp    = (const float*)d_in[10];
    float* out = (float*)d_out;

    float *ph, *pq, *pk, *pv, *po, *ps;
    cudaGetSymbolAddress((void**)&ph, g_h);
    cudaGetSymbolAddress((void**)&pq, g_q);
    cudaGetSymbolAddress((void**)&pk, g_k);
    cudaGetSymbolAddress((void**)&pv, g_v);
    cudaGetSymbolAddress((void**)&po, g_o);
    cudaGetSymbolAddress((void**)&ps, g_s);

    // 1) GroupNorm
    gn_kernel<<<BATCH * GROUPS, 256>>>(x, gamma, beta, ph);

    // 2) Q, K, V: [512x512] @ [512x4096] per batch (NN)
    dim3 gQ(NSP / 128, CCH / 128, BATCH);   // (32, 4, 4)
    sgemm<false, false><<<gQ, 256>>>(wq, ph, pq, CCH, NSP, CCH,
                                     CCH, NSP, NSP, 0, CN, CN, 0,
                                     1.f, bq, nullptr);
    sgemm<false, false><<<gQ, 256>>>(wk, ph, pk, CCH, NSP, CCH,
                                     CCH, NSP, NSP, 0, CN, CN, 0,
                                     1.f, bk, nullptr);
    sgemm<false, false><<<gQ, 256>>>(wv, ph, pv, CCH, NSP, CCH,
                                     CCH, NSP, NSP, 0, CN, CN, 0,
                                     1.f, bv, nullptr);

    // 3) scores = scale * Q^T K : TN, M=N=4096, K=512
    dim3 gS(NSP / 128, NSP / 128, BATCH);   // (32, 32, 4)
    const float scale = 0.04419417382415922f;  // 512^-0.5
    sgemm<true, false><<<gS, 256>>>(pq, pk, ps, NSP, NSP, CCH,
                                    NSP, NSP, NSP, CN, CN, NN, 0,
                                    scale, nullptr, nullptr);

    // 4) softmax over keys (rows of scores)
    softmax_kernel<<<BATCH * NSP, 256>>>(ps);

    // 5) O[c,i] = sum_j V[c,j] * P[i,j] : NT, M=512, N=4096, K=4096
    sgemm<false, true><<<gQ, 256>>>(pv, ps, po, CCH, NSP, NSP,
                                    NSP, NSP, NSP, CN, NN, CN, 0,
                                    1.f, nullptr, nullptr);

    // 6) proj + bias + residual -> d_out
    sgemm<false, false><<<gQ, 256>>>(wp, po, out, CCH, NSP, CCH,
                                     CCH, NSP, NSP, 0, CN, CN, CN,
                                     1.f, bp, x);
}

// round 3
// speedup vs baseline: 2.4929x; 2.4929x over previous
#include <cuda_runtime.h>
#include <cstdint>
#include <math.h>

#define BATCH 4
#define CCH   512
#define NSP   4096
#define GROUPS 32
#define GSIZE  65536

static const long CN  = (long)CCH * NSP;
static const long NNL = (long)NSP * NSP;

// Scratch (device globals — allocation-free per harness rules)
__device__ float g_h [BATCH * CCH * NSP];  // groupnorm output [B][C][N]
__device__ float g_ht[BATCH * CCH * NSP];  // h transposed    [B][N][C]
__device__ float g_q [BATCH * CCH * NSP];  // q_t [B][N][C]
__device__ float g_k [BATCH * CCH * NSP];  // k_t [B][N][C]
__device__ float g_v [BATCH * CCH * NSP];  // v   [B][C][N]
__device__ float g_o [BATCH * CCH * NSP];  // O_t [B][N][C]
__device__ float g_s [BATCH * NSP * NSP];  // scores / attn [B][i][j]

// ===========================================================================
// helpers
// ===========================================================================
__device__ __forceinline__ float f2tf(float f) {
    uint32_t u;
    asm("cvt.rna.tf32.f32 %0, %1;" : "=r"(u) : "f"(f));
    return __uint_as_float(u);
}
__device__ __forceinline__ void cvt4(float4& v) {
    v.x = f2tf(v.x); v.y = f2tf(v.y); v.z = f2tf(v.z); v.w = f2tf(v.w);
}
__device__ __forceinline__ void mma8(float* d, const uint32_t* a, const uint32_t* b) {
    asm volatile(
        "mma.sync.aligned.m16n8k8.row.col.f32.tf32.tf32.f32 "
        "{%0,%1,%2,%3}, {%4,%5,%6,%7}, {%8,%9}, {%0,%1,%2,%3};"
        : "+f"(d[0]), "+f"(d[1]), "+f"(d[2]), "+f"(d[3])
        : "r"(a[0]), "r"(a[1]), "r"(a[2]), "r"(a[3]), "r"(b[0]), "r"(b[1]));
}

// ===========================================================================
// GroupNorm: one block per (b, group), contiguous 65536-float chunk.
// ===========================================================================
__global__ void gn_kernel(const float* __restrict__ x,
                          const float* __restrict__ gamma,
                          const float* __restrict__ beta,
                          float* __restrict__ out)
{
    const int bg  = blockIdx.x;
    const long base = (long)bg * GSIZE;
    const int tid = threadIdx.x;

    float s = 0.f, ss = 0.f;
    for (int i = tid * 4; i < GSIZE; i += 256 * 4) {
        float4 v = *(const float4*)(x + base + i);
        s  += v.x + v.y + v.z + v.w;
        ss += v.x*v.x + v.y*v.y + v.z*v.z + v.w*v.w;
    }
    __shared__ float rs[256], rq[256];
    rs[tid] = s; rq[tid] = ss;
    __syncthreads();
    for (int o = 128; o > 0; o >>= 1) {
        if (tid < o) { rs[tid] += rs[tid + o]; rq[tid] += rq[tid + o]; }
        __syncthreads();
    }
    __shared__ float smu, srstd;
    if (tid == 0) {
        float mu  = rs[0] * (1.f / GSIZE);
        float var = rq[0] * (1.f / GSIZE) - mu * mu;
        smu = mu;
        srstd = rsqrtf(var + 1e-6f);
    }
    __syncthreads();
    const float mu = smu, rstd = srstd;
    const int cbase = (bg & (GROUPS - 1)) * (CCH / GROUPS);

    for (int i = tid * 4; i < GSIZE; i += 256 * 4) {
        float4 v = *(const float4*)(x + base + i);
        int c = cbase + (i >> 12);
        float ga = gamma[c] * rstd;
        float be = beta[c] - mu * ga;
        v.x = v.x * ga + be;
        v.y = v.y * ga + be;
        v.z = v.z * ga + be;
        v.w = v.w * ga + be;
        *(float4*)(out + base + i) = v;
    }
}

// ===========================================================================
// Transpose [C,N] -> [N,C] per batch (32x32 smem tiles)
// ===========================================================================
__global__ void transpose_kernel(const float* __restrict__ in,
                                 float* __restrict__ out)
{
    __shared__ float t[32][33];
    const long off = (long)blockIdx.z * CN;
    const float* I = in + off;
    float* O = out + off;
    const int c0 = blockIdx.y * 32, n0 = blockIdx.x * 32;
    const int x = threadIdx.x, y = threadIdx.y;   // (32, 8)
#pragma unroll
    for (int i = 0; i < 32; i += 8)
        t[y + i][x] = I[(long)(c0 + y + i) * NSP + n0 + x];
    __syncthreads();
#pragma unroll
    for (int i = 0; i < 32; i += 8)
        O[(long)(n0 + y + i) * CCH + c0 + x] = t[x][y + i];
}

// ===========================================================================
// tf32 tensor-core GEMM via mma.sync (sm_80+ path; tcgen05 unavailable on the
// harness's plain-sm_103 ptxas target).
//   D[m,n] = alpha * sum_k A[m*lda+k] * B[n*ldb+k] (+biasM[m]) (+biasN[n]) (+R)
// CTA tile 128x128, K-tile 16, 8 warps (2x4), warp tile 64x32.
// smem stride 20: conflict-free fragment LDS for both A and B patterns.
// ===========================================================================
__global__ void __launch_bounds__(256)
tgemm(const float* __restrict__ A, const float* __restrict__ B,
      float* __restrict__ C, int lda, int ldb, int ldc,
      long sA, long sB, long sC, long sR,
      int K, float alpha,
      const float* __restrict__ biasM, const float* __restrict__ biasN,
      const float* __restrict__ res)
{
    __shared__ float As[2][128 * 20];
    __shared__ float Bs[2][128 * 20];

    const int tid  = threadIdx.x;
    const int lane = tid & 31, wid = tid >> 5;
    const int m0 = blockIdx.y * 128, n0 = blockIdx.x * 128, bz = blockIdx.z;

    const float* Ab = A + bz * sA + (long)m0 * lda;
    const float* Bb = B + bz * sB + (long)n0 * ldb;

    // staging: each thread loads 2 float4 from A and 2 from B per K-tile
    const int r0 = tid >> 2;            // 0..63
    const int c4 = (tid & 3) * 4;       // 0,4,8,12
    const long aS = (long)64 * lda;
    const long bS = (long)64 * ldb;
    const float* pA = Ab + (long)r0 * lda + c4;
    const float* pB = Bb + (long)r0 * ldb + c4;
    const int so0 = r0 * 20 + c4;
    const int so1 = (r0 + 64) * 20 + c4;

    // fragment addressing
    const int qid = lane >> 2, rid = lane & 3;
    const int mw = (wid >> 2) * 64, nw = (wid & 3) * 32;
    const int aBase = (mw + qid) * 20 + rid;
    const int bBase = (nw + qid) * 20 + rid;

    float d[4][4][4];
#pragma unroll
    for (int i = 0; i < 4; i++)
#pragma unroll
        for (int j = 0; j < 4; j++)
#pragma unroll
            for (int l = 0; l < 4; l++) d[i][j][l] = 0.f;

    // prologue: K-tile 0 -> buffer 0
    {
        float4 a0 = *(const float4*)pA;
        float4 a1 = *(const float4*)(pA + aS);
        float4 b0 = *(const float4*)pB;
        float4 b1 = *(const float4*)(pB + bS);
        cvt4(a0); cvt4(a1); cvt4(b0); cvt4(b1);
        *(float4*)&As[0][so0] = a0;
        *(float4*)&As[0][so1] = a1;
        *(float4*)&Bs[0][so0] = b0;
        *(float4*)&Bs[0][so1] = b1;
    }
    __syncthreads();

    const int NK = K >> 4;
#pragma unroll 1
    for (int kt = 0; kt < NK; kt++) {
        const int buf = kt & 1;
        float4 nA0, nA1, nB0, nB1;
        const bool more = (kt + 1 < NK);
        if (more) {
            const float* qa = pA + (kt + 1) * 16;
            const float* qb = pB + (kt + 1) * 16;
            nA0 = *(const float4*)qa;
            nA1 = *(const float4*)(qa + aS);
            nB0 = *(const float4*)qb;
            nB1 = *(const float4*)(qb + bS);
        }

        const uint32_t* Sa = (const uint32_t*)As[buf];
        const uint32_t* Sb = (const uint32_t*)Bs[buf];
#pragma unroll
        for (int ks = 0; ks < 2; ks++) {
            uint32_t af[4][4], bf[4][2];
#pragma unroll
            for (int mi = 0; mi < 4; mi++) {
                const int o = aBase + mi * 320 + ks * 8;
                af[mi][0] = Sa[o];
                af[mi][1] = Sa[o + 160];
                af[mi][2] = Sa[o + 4];
                af[mi][3] = Sa[o + 164];
            }
#pragma unroll
            for (int ni = 0; ni < 4; ni++) {
                const int o = bBase + ni * 160 + ks * 8;
                bf[ni][0] = Sb[o];
                bf[ni][1] = Sb[o + 4];
            }
#pragma unroll
            for (int mi = 0; mi < 4; mi++)
#pragma unroll
                for (int ni = 0; ni < 4; ni++)
                    mma8(d[mi][ni], af[mi], bf[ni]);
        }

        if (more) {
            cvt4(nA0); cvt4(nA1); cvt4(nB0); cvt4(nB1);
            float* da = As[buf ^ 1];
            float* db = Bs[buf ^ 1];
            *(float4*)&da[so0] = nA0;
            *(float4*)&da[so1] = nA1;
            *(float4*)&db[so0] = nB0;
            *(float4*)&db[so1] = nB1;
        }
        __syncthreads();
    }

    // epilogue: coalesced float2 stores
    float* Cb = C + bz * sC;
    const float* Rb = res ? (res + bz * sR) : nullptr;
#pragma unroll
    for (int mi = 0; mi < 4; mi++) {
        const int rA = m0 + mw + mi * 16 + qid;
        const int rB = rA + 8;
        const float bmA = biasM ? biasM[rA] : 0.f;
        const float bmB = biasM ? biasM[rB] : 0.f;
#pragma unroll
        for (int ni = 0; ni < 4; ni++) {
            const int col = n0 + nw + ni * 8 + rid * 2;
            float bn0 = 0.f, bn1 = 0.f;
            if (biasN) { bn0 = biasN[col]; bn1 = biasN[col + 1]; }
            float2 v0, v1;
            v0.x = d[mi][ni][0] * alpha + bmA + bn0;
            v0.y = d[mi][ni][1] * alpha + bmA + bn1;
            v1.x = d[mi][ni][2] * alpha + bmB + bn0;
            v1.y = d[mi][ni][3] * alpha + bmB + bn1;
            const long o0 = (long)rA * ldc + col;
            const long o1 = (long)rB * ldc + col;
            if (Rb) {
                float2 ra = *(const float2*)(Rb + o0);
                float2 rb = *(const float2*)(Rb + o1);
                v0.x += ra.x; v0.y += ra.y;
                v1.x += rb.x; v1.y += rb.y;
            }
            *(float2*)(Cb + o0) = v0;
            *(float2*)(Cb + o1) = v1;
        }
    }
}

// ===========================================================================
// Row softmax over 4096 columns
// ===========================================================================
__global__ void softmax_kernel(float* __restrict__ s)
{
    const long row = blockIdx.x;
    float* p = s + row * (long)NSP;
    const int tid = threadIdx.x;

    __shared__ float buf[NSP];
    __shared__ float red[256];

    float m = -1e30f;
    for (int i = tid * 4; i < NSP; i += 1024) {
        float4 v = *(const float4*)(p + i);
        *(float4*)(buf + i) = v;
        m = fmaxf(m, fmaxf(fmaxf(v.x, v.y), fmaxf(v.z, v.w)));
    }
    red[tid] = m;
    __syncthreads();
    for (int o = 128; o > 0; o >>= 1) {
        if (tid < o) red[tid] = fmaxf(red[tid], red[tid + o]);
        __syncthreads();
    }
    m = red[0];
    __syncthreads();

    float sum = 0.f;
    for (int i = tid * 4; i < NSP; i += 1024) {
        float4 v = *(const float4*)(buf + i);
        v.x = __expf(v.x - m);
        v.y = __expf(v.y - m);
        v.z = __expf(v.z - m);
        v.w = __expf(v.w - m);
        *(float4*)(buf + i) = v;
        sum += v.x + v.y + v.z + v.w;
    }
    red[tid] = sum;
    __syncthreads();
    for (int o = 128; o > 0; o >>= 1) {
        if (tid < o) red[tid] += red[tid + o];
        __syncthreads();
    }
    const float inv = 1.f / red[0];

    for (int i = tid * 4; i < NSP; i += 1024) {
        float4 v = *(const float4*)(buf + i);
        v.x *= inv; v.y *= inv; v.z *= inv; v.w *= inv;
        *(float4*)(p + i) = v;
    }
}

// ===========================================================================
extern "C" void kernel_launch(void* const* d_in, const int* in_sizes, int n_in,
                              void* d_out, int out_size)
{
    const float* x     = (const float*)d_in[0];
    const float* gamma = (const float*)d_in[1];
    const float* beta  = (const float*)d_in[2];
    const float* wq    = (const float*)d_in[3];
    const float* bq    = (const float*)d_in[4];
    const float* wk    = (const float*)d_in[5];
    const float* bk    = (const float*)d_in[6];
    const float* wv    = (const float*)d_in[7];
    const float* bv    = (const float*)d_in[8];
    const float* wp    = (const float*)d_in[9];
    const float* bp    = (const float*)d_in[10];
    float* out = (float*)d_out;

    float *ph, *pht, *pq, *pk, *pv, *po, *ps;
    cudaGetSymbolAddress((void**)&ph,  g_h);
    cudaGetSymbolAddress((void**)&pht, g_ht);
    cudaGetSymbolAddress((void**)&pq,  g_q);
    cudaGetSymbolAddress((void**)&pk,  g_k);
    cudaGetSymbolAddress((void**)&pv,  g_v);
    cudaGetSymbolAddress((void**)&po,  g_o);
    cudaGetSymbolAddress((void**)&ps,  g_s);

    // 1) GroupNorm -> h [C,N]
    gn_kernel<<<BATCH * GROUPS, 256>>>(x, gamma, beta, ph);

    // 2) h -> h_t [N,C]
    dim3 gT(NSP / 32, CCH / 32, BATCH);
    transpose_kernel<<<gT, dim3(32, 8)>>>(ph, pht);

    // 3) q_t[i,o] = sum_c h_t[i,c] wq[o,c] + bq[o]   (M=NSP, N=CCH)
    dim3 gNC(CCH / 128, NSP / 128, BATCH);   // (4, 32, 4)
    tgemm<<<gNC, 256>>>(pht, wq, pq, CCH, CCH, CCH, CN, 0, CN, 0,
                        CCH, 1.f, nullptr, bq, nullptr);
    tgemm<<<gNC, 256>>>(pht, wk, pk, CCH, CCH, CCH, CN, 0, CN, 0,
                        CCH, 1.f, nullptr, bk, nullptr);

    // 4) v[c,j] = sum_c' wv[c,c'] h_t[j,c'] + bv[c]  (M=CCH, N=NSP)
    dim3 gCN(NSP / 128, CCH / 128, BATCH);   // (32, 4, 4)
    tgemm<<<gCN, 256>>>(wv, pht, pv, CCH, CCH, NSP, 0, CN, CN, 0,
                        CCH, 1.f, bv, nullptr, nullptr);

    // 5) scores S[i,j] = scale * sum_c q_t[i,c] k_t[j,c]  (M=N=NSP)
    const float scale = 0.04419417382415922f;  // 512^-0.5
    dim3 gSS(NSP / 128, NSP / 128, BATCH);   // (32, 32, 4)
    tgemm<<<gSS, 256>>>(pq, pk, ps, CCH, CCH, NSP, CN, CN, NNL, 0,
                        CCH, scale, nullptr, nullptr, nullptr);

    // 6) softmax over keys (rows of S)
    softmax_kernel<<<BATCH * NSP, 256>>>(ps);

    // 7) O_t[i,c] = sum_j P[i,j] v[c,j]   (M=NSP, N=CCH, K=NSP)
    tgemm<<<gNC, 256>>>(ps, pv, po, NSP, NSP, CCH, NNL, CN, CN, 0,
                        NSP, 1.f, nullptr, nullptr, nullptr);

    // 8) out[o,n] = sum_c wp[o,c] O_t[n,c] + bp[o] + x[o,n]  (M=CCH, N=NSP)
    tgemm<<<gCN, 256>>>(wp, po, out, CCH, CCH, NSP, 0, CN, CN, CN,
                        CCH, 1.f, bp, nullptr, x);
}

// round 4
// speedup vs baseline: 3.0003x; 1.2035x over previous
#include <cuda_runtime.h>
#include <cstdint>
#include <math.h>

#define BATCH 4
#define CCH   512
#define NSP   4096
#define GROUPS 32
#define GSIZE  65536

static const long CN  = (long)CCH * NSP;
static const long NNL = (long)NSP * NSP;

// Scratch (device globals — allocation-free per harness rules)
__device__ float g_h [BATCH * CCH * NSP];  // groupnorm output [B][C][N]
__device__ float g_ht[BATCH * CCH * NSP];  // h transposed    [B][N][C]
__device__ float g_q [BATCH * CCH * NSP];  // q_t [B][N][C]
__device__ float g_k [BATCH * CCH * NSP];  // k_t [B][N][C]
__device__ float g_v [BATCH * CCH * NSP];  // v   [B][C][N]
__device__ float g_o [BATCH * CCH * NSP];  // O_t [B][N][C]
__device__ float g_s [BATCH * NSP * NSP];  // scores / attn [B][i][j]

// ===========================================================================
// helpers
// ===========================================================================
__device__ __forceinline__ float f2tf(float f) {
    uint32_t u;
    asm("cvt.rna.tf32.f32 %0, %1;" : "=r"(u) : "f"(f));
    return __uint_as_float(u);
}
__device__ __forceinline__ void cvt4(float4& v) {
    v.x = f2tf(v.x); v.y = f2tf(v.y); v.z = f2tf(v.z); v.w = f2tf(v.w);
}
__device__ __forceinline__ uint32_t s2u(const void* p) {
    uint32_t a;
    asm("{ .reg .u64 t; cvta.to.shared.u64 t, %1; cvt.u32.u64 %0, t; }"
        : "=r"(a) : "l"(p));
    return a;
}
__device__ __forceinline__ void mma8(float* d, const uint32_t* a, const uint32_t* b) {
    asm volatile(
        "mma.sync.aligned.m16n8k8.row.col.f32.tf32.tf32.f32 "
        "{%0,%1,%2,%3}, {%4,%5,%6,%7}, {%8,%9}, {%0,%1,%2,%3};"
        : "+f"(d[0]), "+f"(d[1]), "+f"(d[2]), "+f"(d[3])
        : "r"(a[0]), "r"(a[1]), "r"(a[2]), "r"(a[3]), "r"(b[0]), "r"(b[1]));
}
// ldmatrix x4: loads four 8x8 b16 matrices (== four 8x4 tf32 chunks)
__device__ __forceinline__ void ldm4(uint32_t* r, uint32_t addr) {
    asm volatile(
        "ldmatrix.sync.aligned.m8n8.x4.shared.b16 {%0,%1,%2,%3}, [%4];"
        : "=r"(r[0]), "=r"(r[1]), "=r"(r[2]), "=r"(r[3]) : "r"(addr));
}

// ===========================================================================
// GroupNorm: one block per (b, group), contiguous 65536-float chunk.
// ===========================================================================
__global__ void gn_kernel(const float* __restrict__ x,
                          const float* __restrict__ gamma,
                          const float* __restrict__ beta,
                          float* __restrict__ out)
{
    const int bg  = blockIdx.x;
    const long base = (long)bg * GSIZE;
    const int tid = threadIdx.x;

    float s = 0.f, ss = 0.f;
    for (int i = tid * 4; i < GSIZE; i += 256 * 4) {
        float4 v = *(const float4*)(x + base + i);
        s  += v.x + v.y + v.z + v.w;
        ss += v.x*v.x + v.y*v.y + v.z*v.z + v.w*v.w;
    }
    __shared__ float rs[256], rq[256];
    rs[tid] = s; rq[tid] = ss;
    __syncthreads();
    for (int o = 128; o > 0; o >>= 1) {
        if (tid < o) { rs[tid] += rs[tid + o]; rq[tid] += rq[tid + o]; }
        __syncthreads();
    }
    __shared__ float smu, srstd;
    if (tid == 0) {
        float mu  = rs[0] * (1.f / GSIZE);
        float var = rq[0] * (1.f / GSIZE) - mu * mu;
        smu = mu;
        srstd = rsqrtf(var + 1e-6f);
    }
    __syncthreads();
    const float mu = smu, rstd = srstd;
    const int cbase = (bg & (GROUPS - 1)) * (CCH / GROUPS);

    for (int i = tid * 4; i < GSIZE; i += 256 * 4) {
        float4 v = *(const float4*)(x + base + i);
        int c = cbase + (i >> 12);
        float ga = gamma[c] * rstd;
        float be = beta[c] - mu * ga;
        v.x = v.x * ga + be;
        v.y = v.y * ga + be;
        v.z = v.z * ga + be;
        v.w = v.w * ga + be;
        *(float4*)(out + base + i) = v;
    }
}

// ===========================================================================
// Transpose [C,N] -> [N,C] per batch (32x32 smem tiles)
// ===========================================================================
__global__ void transpose_kernel(const float* __restrict__ in,
                                 float* __restrict__ out)
{
    __shared__ float t[32][33];
    const long off = (long)blockIdx.z * CN;
    const float* I = in + off;
    float* O = out + off;
    const int c0 = blockIdx.y * 32, n0 = blockIdx.x * 32;
    const int x = threadIdx.x, y = threadIdx.y;   // (32, 8)
#pragma unroll
    for (int i = 0; i < 32; i += 8)
        t[y + i][x] = I[(long)(c0 + y + i) * NSP + n0 + x];
    __syncthreads();
#pragma unroll
    for (int i = 0; i < 32; i += 8)
        O[(long)(n0 + y + i) * CCH + c0 + x] = t[x][y + i];
}

// ===========================================================================
// tf32 tensor-core GEMM via mma.sync + ldmatrix.
//   D[m,n] = alpha * sum_k A[m*lda+k] * B[n*ldb+k] (+biasM[m]) (+biasN[n]) (+R)
// CTA tile 128x128, K-tile 16, 8 warps (2x4), warp tile 64x32.
// smem row stride 20 floats: 8 rows at stride 20 cover all 32 banks ->
// conflict-free ldmatrix phases; 16B alignment holds (80B rows).
// ===========================================================================
__global__ void __launch_bounds__(256)
tgemm(const float* __restrict__ A, const float* __restrict__ B,
      float* __restrict__ C, int lda, int ldb, int ldc,
      long sA, long sB, long sC, long sR,
      int K, float alpha,
      const float* __restrict__ biasM, const float* __restrict__ biasN,
      const float* __restrict__ res)
{
    __shared__ float As[2][128 * 20];
    __shared__ float Bs[2][128 * 20];

    const int tid  = threadIdx.x;
    const int lane = tid & 31, wid = tid >> 5;
    const int m0 = blockIdx.y * 128, n0 = blockIdx.x * 128, bz = blockIdx.z;

    const float* Ab = A + bz * sA + (long)m0 * lda;
    const float* Bb = B + bz * sB + (long)n0 * ldb;

    // staging: each thread loads 2 float4 from A and 2 from B per K-tile
    const int r0 = tid >> 2;            // 0..63
    const int c4 = (tid & 3) * 4;       // 0,4,8,12
    const long aS = (long)64 * lda;
    const long bS = (long)64 * ldb;
    const float* pA = Ab + (long)r0 * lda + c4;
    const float* pB = Bb + (long)r0 * ldb + c4;
    const int so0 = r0 * 20 + c4;
    const int so1 = (r0 + 64) * 20 + c4;

    // warp/fragment addressing
    const int qid = lane >> 2, rid = lane & 3;
    const int mw = (wid >> 2) * 64, nw = (wid & 3) * 32;

    // ldmatrix source addresses (bytes).
    // A x4 for (mi,ks): matrices = {rows+0..7,ck}, {rows+8..15,ck},
    //                               {rows+0..7,ck+1}, {rows+8..15,ck+1}
    //   -> regs {a0,a1,a2,a3}. thread lane: row = lane&15, chunk += lane>>4.
    const uint32_t aLD = s2u(&As[0][0]) + (uint32_t)(mw + (lane & 15)) * 80u
                       + (uint32_t)(lane >> 4) * 16u;
    // B x4 for ni: matrices = chunks 0..3 of rows nw+ni*8..+7
    //   -> regs {b_ks0_0, b_ks0_1, b_ks1_0, b_ks1_1}.
    const uint32_t bLD = s2u(&Bs[0][0]) + (uint32_t)(nw + (lane & 7)) * 80u
                       + (uint32_t)(lane >> 3) * 16u;

    float d[4][4][4];
#pragma unroll
    for (int i = 0; i < 4; i++)
#pragma unroll
        for (int j = 0; j < 4; j++)
#pragma unroll
            for (int l = 0; l < 4; l++) d[i][j][l] = 0.f;

    // prologue: K-tile 0 -> buffer 0
    {
        float4 a0 = *(const float4*)pA;
        float4 a1 = *(const float4*)(pA + aS);
        float4 b0 = *(const float4*)pB;
        float4 b1 = *(const float4*)(pB + bS);
        cvt4(a0); cvt4(a1); cvt4(b0); cvt4(b1);
        *(float4*)&As[0][so0] = a0;
        *(float4*)&As[0][so1] = a1;
        *(float4*)&Bs[0][so0] = b0;
        *(float4*)&Bs[0][so1] = b1;
    }
    __syncthreads();

    const int NK = K >> 4;
#pragma unroll 1
    for (int kt = 0; kt < NK; kt++) {
        const uint32_t bufo = (uint32_t)(kt & 1) * 10240u;  // 128*20*4 bytes
        float4 nA0, nA1, nB0, nB1;
        const bool more = (kt + 1 < NK);
        if (more) {
            const float* qa = pA + (kt + 1) * 16;
            const float* qb = pB + (kt + 1) * 16;
            nA0 = *(const float4*)qa;
            nA1 = *(const float4*)(qa + aS);
            nB0 = *(const float4*)qb;
            nB1 = *(const float4*)(qb + bS);
        }

        // B fragments for both k-steps: 4 ldmatrix.x4
        uint32_t bf[4][4];
#pragma unroll
        for (int ni = 0; ni < 4; ni++)
            ldm4(bf[ni], bLD + bufo + (uint32_t)ni * 640u);

#pragma unroll
        for (int ks = 0; ks < 2; ks++) {
            uint32_t af[4][4];
#pragma unroll
            for (int mi = 0; mi < 4; mi++)
                ldm4(af[mi], aLD + bufo + (uint32_t)mi * 1280u
                                   + (uint32_t)ks * 32u);
#pragma unroll
            for (int mi = 0; mi < 4; mi++)
#pragma unroll
                for (int ni = 0; ni < 4; ni++)
                    mma8(d[mi][ni], af[mi], &bf[ni][ks * 2]);
        }

        if (more) {
            cvt4(nA0); cvt4(nA1); cvt4(nB0); cvt4(nB1);
            float* da = As[(kt & 1) ^ 1];
            float* db = Bs[(kt & 1) ^ 1];
            *(float4*)&da[so0] = nA0;
            *(float4*)&da[so1] = nA1;
            *(float4*)&db[so0] = nB0;
            *(float4*)&db[so1] = nB1;
        }
        __syncthreads();
    }

    // epilogue: coalesced float2 stores
    float* Cb = C + bz * sC;
    const float* Rb = res ? (res + bz * sR) : nullptr;
#pragma unroll
    for (int mi = 0; mi < 4; mi++) {
        const int rA = m0 + mw + mi * 16 + qid;
        const int rB = rA + 8;
        const float bmA = biasM ? biasM[rA] : 0.f;
        const float bmB = biasM ? biasM[rB] : 0.f;
#pragma unroll
        for (int ni = 0; ni < 4; ni++) {
            const int col = n0 + nw + ni * 8 + rid * 2;
            float bn0 = 0.f, bn1 = 0.f;
            if (biasN) { bn0 = biasN[col]; bn1 = biasN[col + 1]; }
            float2 v0, v1;
            v0.x = d[mi][ni][0] * alpha + bmA + bn0;
            v0.y = d[mi][ni][1] * alpha + bmA + bn1;
            v1.x = d[mi][ni][2] * alpha + bmB + bn0;
            v1.y = d[mi][ni][3] * alpha + bmB + bn1;
            const long o0 = (long)rA * ldc + col;
            const long o1 = (long)rB * ldc + col;
            if (Rb) {
                float2 ra = *(const float2*)(Rb + o0);
                float2 rb = *(const float2*)(Rb + o1);
                v0.x += ra.x; v0.y += ra.y;
                v1.x += rb.x; v1.y += rb.y;
            }
            *(float2*)(Cb + o0) = v0;
            *(float2*)(Cb + o1) = v1;
        }
    }
}

// ===========================================================================
// Row softmax over 4096 columns
// ===========================================================================
__global__ void softmax_kernel(float* __restrict__ s)
{
    const long row = blockIdx.x;
    float* p = s + row * (long)NSP;
    const int tid = threadIdx.x;

    __shared__ float buf[NSP];
    __shared__ float red[256];

    float m = -1e30f;
    for (int i = tid * 4; i < NSP; i += 1024) {
        float4 v = *(const float4*)(p + i);
        *(float4*)(buf + i) = v;
        m = fmaxf(m, fmaxf(fmaxf(v.x, v.y), fmaxf(v.z, v.w)));
    }
    red[tid] = m;
    __syncthreads();
    for (int o = 128; o > 0; o >>= 1) {
        if (tid < o) red[tid] = fmaxf(red[tid], red[tid + o]);
        __syncthreads();
    }
    m = red[0];
    __syncthreads();

    float sum = 0.f;
    for (int i = tid * 4; i < NSP; i += 1024) {
        float4 v = *(const float4*)(buf + i);
        v.x = __expf(v.x - m);
        v.y = __expf(v.y - m);
        v.z = __expf(v.z - m);
        v.w = __expf(v.w - m);
        *(float4*)(buf + i) = v;
        sum += v.x + v.y + v.z + v.w;
    }
    red[tid] = sum;
    __syncthreads();
    for (int o = 128; o > 0; o >>= 1) {
        if (tid < o) red[tid] += red[tid + o];
        __syncthreads();
    }
    const float inv = 1.f / red[0];

    for (int i = tid * 4; i < NSP; i += 1024) {
        float4 v = *(const float4*)(buf + i);
        v.x *= inv; v.y *= inv; v.z *= inv; v.w *= inv;
        *(float4*)(p + i) = v;
    }
}

// ===========================================================================
extern "C" void kernel_launch(void* const* d_in, const int* in_sizes, int n_in,
                              void* d_out, int out_size)
{
    const float* x     = (const float*)d_in[0];
    const float* gamma = (const float*)d_in[1];
    const float* beta  = (const float*)d_in[2];
    const float* wq    = (const float*)d_in[3];
    const float* bq    = (const float*)d_in[4];
    const float* wk    = (const float*)d_in[5];
    const float* bk    = (const float*)d_in[6];
    const float* wv    = (const float*)d_in[7];
    const float* bv    = (const float*)d_in[8];
    const float* wp    = (const float*)d_in[9];
    const float* bp    = (const float*)d_in[10];
    float* out = (float*)d_out;

    float *ph, *pht, *pq, *pk, *pv, *po, *ps;
    cudaGetSymbolAddress((void**)&ph,  g_h);
    cudaGetSymbolAddress((void**)&pht, g_ht);
    cudaGetSymbolAddress((void**)&pq,  g_q);
    cudaGetSymbolAddress((void**)&pk,  g_k);
    cudaGetSymbolAddress((void**)&pv,  g_v);
    cudaGetSymbolAddress((void**)&po,  g_o);
    cudaGetSymbolAddress((void**)&ps,  g_s);

    // 1) GroupNorm -> h [C,N]
    gn_kernel<<<BATCH * GROUPS, 256>>>(x, gamma, beta, ph);

    // 2) h -> h_t [N,C]
    dim3 gT(NSP / 32, CCH / 32, BATCH);
    transpose_kernel<<<gT, dim3(32, 8)>>>(ph, pht);

    // 3) q_t[i,o] = sum_c h_t[i,c] wq[o,c] + bq[o]   (M=NSP, N=CCH)
    dim3 gNC(CCH / 128, NSP / 128, BATCH);   // (4, 32, 4)
    tgemm<<<gNC, 256>>>(pht, wq, pq, CCH, CCH, CCH, CN, 0, CN, 0,
                        CCH, 1.f, nullptr, bq, nullptr);
    tgemm<<<gNC, 256>>>(pht, wk, pk, CCH, CCH, CCH, CN, 0, CN, 0,
                        CCH, 1.f, nullptr, bk, nullptr);

    // 4) v[c,j] = sum_c' wv[c,c'] h_t[j,c'] + bv[c]  (M=CCH, N=NSP)
    dim3 gCN(NSP / 128, CCH / 128, BATCH);   // (32, 4, 4)
    tgemm<<<gCN, 256>>>(wv, pht, pv, CCH, CCH, NSP, 0, CN, CN, 0,
                        CCH, 1.f, bv, nullptr, nullptr);

    // 5) scores S[i,j] = scale * sum_c q_t[i,c] k_t[j,c]  (M=N=NSP)
    const float scale = 0.04419417382415922f;  // 512^-0.5
    dim3 gSS(NSP / 128, NSP / 128, BATCH);   // (32, 32, 4)
    tgemm<<<gSS, 256>>>(pq, pk, ps, CCH, CCH, NSP, CN, CN, NNL, 0,
                        CCH, scale, nullptr, nullptr, nullptr);

    // 6) softmax over keys (rows of S)
    softmax_kernel<<<BATCH * NSP, 256>>>(ps);

    // 7) O_t[i,c] = sum_j P[i,j] v[c,j]   (M=NSP, N=CCH, K=NSP)
    tgemm<<<gNC, 256>>>(ps, pv, po, NSP, NSP, CCH, NNL, CN, CN, 0,
                        NSP, 1.f, nullptr, nullptr, nullptr);

    // 8) out[o,n] = sum_c wp[o,c] O_t[n,c] + bp[o] + x[o,n]  (M=CCH, N=NSP)
    tgemm<<<gCN, 256>>>(wp, po, out, CCH, CCH, NSP, 0, CN, CN, CN,
                        CCH, 1.f, bp, nullptr, x);
}